// round 1
// baseline (speedup 1.0000x reference)
#include <cuda_runtime.h>
#include <math.h>

// ContrastiveLoss N=8192 D=128 temp=0.05
// loss = -mean_i [ (1/ppn_i) * sum_{j: y_ij=1} log( e_ij / (e_ij + nl_i) ) ]
// where e_ij = exp(cos_ij/T), nl_i = sum_j e_ij*(1-y_ij)
// Note: log(e/(e+nl)) = -log1p(nl*exp(-t)), t = cos/T.

#define NN 8192
#define DD 128
#define INV_T 20.0f
#define MAX_POS 768
#define NTILES 64   // NN/128

__device__ float g_xn[NN * DD];                       // normalized x
__device__ float g_nl_part[(size_t)NN * NTILES];      // per-(row,colTile) negative mass
__device__ int   g_cnt[NN];                           // positives per row
__device__ float g_pos[(size_t)NN * MAX_POS];         // t = cos/T for positives
__device__ float g_lm[NN];                            // per-row loss contribution (positive sign)

// ---------------------------------------------------------------------------
// Kernel 1: L2-normalize rows of x; also zero the per-row positive counters.
// One warp per row.
__global__ void k_normalize(const float* __restrict__ x) {
    int row  = blockIdx.x * 8 + (threadIdx.x >> 5);
    int lane = threadIdx.x & 31;
    float4 v = ((const float4*)(x + (size_t)row * DD))[lane];
    float ss = v.x * v.x + v.y * v.y + v.z * v.z + v.w * v.w;
    #pragma unroll
    for (int o = 16; o; o >>= 1) ss += __shfl_xor_sync(0xFFFFFFFFu, ss, o);
    float inv = 1.0f / sqrtf(ss);
    float4 o4;
    o4.x = v.x * inv; o4.y = v.y * inv; o4.z = v.z * inv; o4.w = v.w * inv;
    ((float4*)(g_xn + (size_t)row * DD))[lane] = o4;
    if (lane == 0) g_cnt[row] = 0;
}

// ---------------------------------------------------------------------------
// Kernel 2: fused tile GEMM + epilogue.
// Each block computes a 128x128 tile of S = xn @ xn^T (full K=128),
// then: e = exp(S*20); accumulates per-row negative mass into g_nl_part
// (deterministic, one slot per (row, colTile)); captures t for positives.
__global__ __launch_bounds__(256) void k_tile(const float* __restrict__ y) {
    __shared__ float a_s[16][132];
    __shared__ float b_s[16][132];
    __shared__ float red[128][17];

    const int tx = threadIdx.x & 15;
    const int ty = threadIdx.x >> 4;
    const int row0 = blockIdx.y * 128;
    const int col0 = blockIdx.x * 128;

    float acc[8][8];
    #pragma unroll
    for (int i = 0; i < 8; i++)
        #pragma unroll
        for (int j = 0; j < 8; j++) acc[i][j] = 0.0f;

    for (int k0 = 0; k0 < DD; k0 += 16) {
        // load A (rows) and B (cols) chunks, transposed into [k][r]
        #pragma unroll
        for (int it = 0; it < 2; it++) {
            int idx = threadIdx.x + it * 256;   // 0..511
            int r   = idx >> 2;                 // 0..127
            int kq  = (idx & 3) << 2;           // 0,4,8,12
            float4 va = *(const float4*)&g_xn[(size_t)(row0 + r) * DD + k0 + kq];
            a_s[kq + 0][r] = va.x; a_s[kq + 1][r] = va.y;
            a_s[kq + 2][r] = va.z; a_s[kq + 3][r] = va.w;
            float4 vb = *(const float4*)&g_xn[(size_t)(col0 + r) * DD + k0 + kq];
            b_s[kq + 0][r] = vb.x; b_s[kq + 1][r] = vb.y;
            b_s[kq + 2][r] = vb.z; b_s[kq + 3][r] = vb.w;
        }
        __syncthreads();
        #pragma unroll
        for (int k = 0; k < 16; k++) {
            float a[8], b[8];
            #pragma unroll
            for (int i = 0; i < 8; i++) a[i] = a_s[k][ty + i * 16];
            #pragma unroll
            for (int j = 0; j < 8; j++) b[j] = b_s[k][tx + j * 16];
            #pragma unroll
            for (int i = 0; i < 8; i++)
                #pragma unroll
                for (int j = 0; j < 8; j++)
                    acc[i][j] = fmaf(a[i], b[j], acc[i][j]);
        }
        __syncthreads();
    }

    // Epilogue: exp, negative mass, positive capture
    float rowpart[8];
    #pragma unroll
    for (int i = 0; i < 8; i++) {
        rowpart[i] = 0.0f;
        int row = row0 + ty + i * 16;
        const float* yrow = y + (size_t)row * NN + col0;
        #pragma unroll
        for (int j = 0; j < 8; j++) {
            int c   = tx + j * 16;
            float t = acc[i][j] * INV_T;
            float e = __expf(t);
            float yv = yrow[c];
            rowpart[i] += e * (1.0f - yv);
            if (yv != 0.0f) {
                int slot = atomicAdd(&g_cnt[row], 1);
                if (slot < MAX_POS)
                    g_pos[(size_t)row * MAX_POS + slot] = t;
            }
        }
    }

    // Reduce rowpart across the 16 tx lanes -> one partial per row per tile
    #pragma unroll
    for (int i = 0; i < 8; i++) red[ty + i * 16][tx] = rowpart[i];
    __syncthreads();
    if (threadIdx.x < 128) {
        float s = 0.0f;
        #pragma unroll
        for (int c = 0; c < 16; c++) s += red[threadIdx.x][c];
        g_nl_part[(size_t)(row0 + threadIdx.x) * NTILES + blockIdx.x] = s;
    }
}

// ---------------------------------------------------------------------------
// Kernel 3: per-row loss. One warp per row.
// g_lm[row] = (1/cnt) * sum_p log1p(nl * exp(-t_p))   (positive sign)
__global__ void k_rowloss() {
    int row  = blockIdx.x * 8 + (threadIdx.x >> 5);
    int lane = threadIdx.x & 31;
    const float* p = g_nl_part + (size_t)row * NTILES;
    float nl = p[lane] + p[lane + 32];
    #pragma unroll
    for (int o = 16; o; o >>= 1) nl += __shfl_xor_sync(0xFFFFFFFFu, nl, o);

    int cnt = g_cnt[row];
    const float* ps = g_pos + (size_t)row * MAX_POS;
    float acc = 0.0f;
    for (int i = lane; i < cnt; i += 32) {
        float t = ps[i];
        acc += log1pf(nl * __expf(-t));
    }
    #pragma unroll
    for (int o = 16; o; o >>= 1) acc += __shfl_xor_sync(0xFFFFFFFFu, acc, o);
    if (lane == 0) g_lm[row] = acc / (float)cnt;
}

// ---------------------------------------------------------------------------
// Kernel 4: final mean. loss = mean(g_lm).
__global__ void k_final(float* __restrict__ out) {
    __shared__ float sm[256];
    float s = 0.0f;
    for (int i = threadIdx.x; i < NN; i += 256) s += g_lm[i];
    sm[threadIdx.x] = s;
    __syncthreads();
    for (int o = 128; o; o >>= 1) {
        if (threadIdx.x < o) sm[threadIdx.x] += sm[threadIdx.x + o];
        __syncthreads();
    }
    if (threadIdx.x == 0) out[0] = sm[0] / (float)NN;
}

// ---------------------------------------------------------------------------
extern "C" void kernel_launch(void* const* d_in, const int* in_sizes, int n_in,
                              void* d_out, int out_size) {
    const float* x = (const float*)d_in[0];
    const float* y = (const float*)d_in[1];

    k_normalize<<<NN / 8, 256>>>(x);
    dim3 grid(NTILES, NTILES);
    k_tile<<<grid, 256>>>(y);
    k_rowloss<<<NN / 8, 256>>>();
    k_final<<<1, 256>>>((float*)d_out);
}

// round 3
// speedup vs baseline: 1.4119x; 1.4119x over previous
#include <cuda_runtime.h>
#include <cuda_bf16.h>
#include <math.h>
#include <cstdint>

// ContrastiveLoss N=8192 D=128 temp=0.05 — bf16-split HMMA (mma.sync) version
// loss = -mean_i [ (1/ppn_i) * sum_{j: y_ij=1} log( e_ij / (e_ij + nl_i) ) ]
// e_ij = exp(cos_ij/T);  nl_i = sum_j e_ij*(1-y_ij)
// log(e/(e+nl)) = -log1p(nl*exp(-t)), t = cos/T.
// cos ~= hi.hi^T + hi.lo^T  (bf16 split; dropped lo.hi^T ~9e-5 on cos)

#define NN 8192
#define DD 128
#define INV_T 20.0f
#define MAX_POS 768
#define NTILES 64            // NN/128 column tiles
#define NWORDS (NN / 32)     // 256 bitmask words per row

__device__ __nv_bfloat16 g_xhi[NN * DD];
__device__ __nv_bfloat16 g_xlo[NN * DD];
__device__ unsigned g_ybits[(size_t)NN * NWORDS];
__device__ float g_nl_part[(size_t)NN * NTILES * 2];   // 128 partials per row
__device__ int   g_cnt[NN];
__device__ float g_pos[(size_t)NN * MAX_POS];
__device__ float g_lm[NN];

// ---------------------------------------------------------------------------
__device__ __forceinline__ uint32_t smem_u32(const void* p) {
    uint32_t a;
    asm("{ .reg .u64 t; cvta.to.shared.u64 t, %1; cvt.u32.u64 %0, t; }" : "=r"(a) : "l"(p));
    return a;
}
__device__ __forceinline__ void ldmx4(uint32_t* r, uint32_t addr) {
    asm volatile("ldmatrix.sync.aligned.m8n8.x4.shared.b16 {%0,%1,%2,%3}, [%4];"
        : "=r"(r[0]), "=r"(r[1]), "=r"(r[2]), "=r"(r[3]) : "r"(addr));
}
__device__ __forceinline__ void mma_bf16(float* d, const uint32_t* a,
                                         uint32_t b0, uint32_t b1) {
    asm volatile("mma.sync.aligned.m16n8k16.row.col.f32.bf16.bf16.f32 "
        "{%0,%1,%2,%3}, {%4,%5,%6,%7}, {%8,%9}, {%0,%1,%2,%3};"
        : "+f"(d[0]), "+f"(d[1]), "+f"(d[2]), "+f"(d[3])
        : "r"(a[0]), "r"(a[1]), "r"(a[2]), "r"(a[3]), "r"(b0), "r"(b1));
}

// ---------------------------------------------------------------------------
// Kernel 0: binarize y into bitmask.
__global__ void k_ybits(const float* __restrict__ y) {
    size_t idx = (size_t)blockIdx.x * blockDim.x + threadIdx.x;
    unsigned w = __ballot_sync(0xFFFFFFFFu, y[idx] != 0.0f);
    if ((threadIdx.x & 31) == 0) g_ybits[idx >> 5] = w;
}

// ---------------------------------------------------------------------------
// Kernel 1: normalize rows, split into bf16 hi/lo; zero counters.
__global__ void k_normalize(const float* __restrict__ x) {
    int row  = blockIdx.x * 8 + (threadIdx.x >> 5);
    int lane = threadIdx.x & 31;
    float4 v = ((const float4*)(x + (size_t)row * DD))[lane];
    float ss = v.x * v.x + v.y * v.y + v.z * v.z + v.w * v.w;
    #pragma unroll
    for (int o = 16; o; o >>= 1) ss += __shfl_xor_sync(0xFFFFFFFFu, ss, o);
    float inv = rsqrtf(ss);
    float f[4] = {v.x * inv, v.y * inv, v.z * inv, v.w * inv};
    ushort4 hi4, lo4;
    unsigned short* hp = &hi4.x;
    unsigned short* lp = &lo4.x;
    #pragma unroll
    for (int i = 0; i < 4; i++) {
        __nv_bfloat16 h = __float2bfloat16(f[i]);
        __nv_bfloat16 l = __float2bfloat16(f[i] - __bfloat162float(h));
        hp[i] = *(unsigned short*)&h;
        lp[i] = *(unsigned short*)&l;
    }
    ((ushort4*)(g_xhi + (size_t)row * DD))[lane] = hi4;
    ((ushort4*)(g_xlo + (size_t)row * DD))[lane] = lo4;
    if (lane == 0) g_cnt[row] = 0;
}

// ---------------------------------------------------------------------------
// Kernel 2: HMMA tile GEMM + fused epilogue.
// SMEM layout (bytes): A_hi@0 (32K), B_hi@32768 (32K), B_lo@65536 (32K),
// ybits@98304 (2K). Rows are 256B; 16B chunk c of row r stored at c^(r&7).
#define SM_A   0
#define SM_BH  32768
#define SM_BL  65536
#define SM_YB  98304
#define SM_TOT 100352

__global__ void __launch_bounds__(256, 2) k_tile() {
    extern __shared__ char smem[];
    uint32_t sbase = smem_u32(smem);
    const int tid  = threadIdx.x;
    const int wid  = tid >> 5;
    const int lane = tid & 31;
    const int warp_m = wid >> 1;     // 0..3  (32 rows each)
    const int warp_n = wid & 1;      // 0..1  (64 cols each)
    const int row0 = blockIdx.y * 128;
    const int col0 = blockIdx.x * 128;

    // ---- load tiles: 2048 uint4 per operand; chunk-swizzled stores
    {
        const uint4* ah = (const uint4*)(g_xhi + (size_t)row0 * DD);
        const uint4* bh = (const uint4*)(g_xhi + (size_t)col0 * DD);
        const uint4* bl = (const uint4*)(g_xlo + (size_t)col0 * DD);
        #pragma unroll
        for (int i = 0; i < 8; i++) {
            int idx = tid + i * 256;            // 0..2047
            int r   = idx >> 4;                 // 0..127
            int c   = idx & 15;                 // 16B chunk
            uint32_t so = (uint32_t)r * 256 + (uint32_t)((c ^ (r & 7)) * 16);
            *(uint4*)(smem + SM_A  + so) = ah[idx];
            *(uint4*)(smem + SM_BH + so) = bh[idx];
            *(uint4*)(smem + SM_BL + so) = bl[idx];
        }
        // stage y bitmask: 128 rows x 4 words
        unsigned* yb = (unsigned*)(smem + SM_YB);
        for (int i = tid; i < 512; i += 256) {
            int r = i >> 2, w = i & 3;
            yb[i] = g_ybits[(size_t)(row0 + r) * NWORDS + blockIdx.x * 4 + w];
        }
    }
    __syncthreads();

    // ---- mainloop
    float acc[2][8][4];
    #pragma unroll
    for (int i = 0; i < 2; i++)
        #pragma unroll
        for (int j = 0; j < 8; j++)
            #pragma unroll
            for (int q = 0; q < 4; q++) acc[i][j][q] = 0.0f;

    const uint32_t lane_row = lane & 15;
    const uint32_t kb  = lane >> 4;          // 0/1
    const uint32_t key = lane & 7;           // swizzle key (row&7)
    const uint32_t a_base = sbase + SM_A  + (warp_m * 32 + lane_row) * 256;
    const uint32_t b_base = sbase + SM_BH + (warp_n * 64 + lane_row) * 256;

    #pragma unroll
    for (int k16 = 0; k16 < 8; k16++) {
        uint32_t ca = (((uint32_t)k16 * 2 + kb) ^ key) * 16;
        uint32_t a0[4], a1[4];
        ldmx4(a0, a_base + ca);
        ldmx4(a1, a_base + 4096 + ca);
        #pragma unroll
        for (int n16 = 0; n16 < 4; n16++) {
            uint32_t bf[4];
            ldmx4(bf, b_base + n16 * 4096 + ca);            // B_hi
            mma_bf16(acc[0][n16 * 2 + 0], a0, bf[0], bf[2]);
            mma_bf16(acc[0][n16 * 2 + 1], a0, bf[1], bf[3]);
            mma_bf16(acc[1][n16 * 2 + 0], a1, bf[0], bf[2]);
            mma_bf16(acc[1][n16 * 2 + 1], a1, bf[1], bf[3]);
            ldmx4(bf, b_base + 32768 + n16 * 4096 + ca);    // B_lo
            mma_bf16(acc[0][n16 * 2 + 0], a0, bf[0], bf[2]);
            mma_bf16(acc[0][n16 * 2 + 1], a0, bf[1], bf[3]);
            mma_bf16(acc[1][n16 * 2 + 0], a1, bf[0], bf[2]);
            mma_bf16(acc[1][n16 * 2 + 1], a1, bf[1], bf[3]);
        }
    }

    // ---- epilogue: exp, negative mass, positive capture
    const unsigned* yb = (const unsigned*)(smem + SM_YB);
    const int qm = lane >> 2;            // 0..7
    const int qn = (lane & 3) * 2;       // 0,2,4,6
    float neg[2][2] = {{0.f, 0.f}, {0.f, 0.f}};

    #pragma unroll
    for (int m_i = 0; m_i < 2; m_i++) {
        int rlo = warp_m * 32 + m_i * 16 + qm;   // local row
        int rhi = rlo + 8;
        int grow_lo = row0 + rlo;
        int grow_hi = row0 + rhi;
        #pragma unroll
        for (int n8 = 0; n8 < 8; n8++) {
            int cl = warp_n * 64 + n8 * 8 + qn;  // local col (pair base)
            int w  = cl >> 5;
            unsigned wlo = yb[rlo * 4 + w];
            unsigned whi = yb[rhi * 4 + w];
            unsigned b0 = 1u << (cl & 31);
            unsigned b1 = b0 << 1;
            const float* d = acc[m_i][n8];
            float t0 = d[0] * INV_T, t1 = d[1] * INV_T;
            float t2 = d[2] * INV_T, t3 = d[3] * INV_T;
            float e0 = __expf(t0), e1 = __expf(t1);
            float e2 = __expf(t2), e3 = __expf(t3);
            if (wlo & b0) {
                int s = atomicAdd(&g_cnt[grow_lo], 1);
                if (s < MAX_POS) g_pos[(size_t)grow_lo * MAX_POS + s] = t0;
            } else neg[m_i][0] += e0;
            if (wlo & b1) {
                int s = atomicAdd(&g_cnt[grow_lo], 1);
                if (s < MAX_POS) g_pos[(size_t)grow_lo * MAX_POS + s] = t1;
            } else neg[m_i][0] += e1;
            if (whi & b0) {
                int s = atomicAdd(&g_cnt[grow_hi], 1);
                if (s < MAX_POS) g_pos[(size_t)grow_hi * MAX_POS + s] = t2;
            } else neg[m_i][1] += e2;
            if (whi & b1) {
                int s = atomicAdd(&g_cnt[grow_hi], 1);
                if (s < MAX_POS) g_pos[(size_t)grow_hi * MAX_POS + s] = t3;
            } else neg[m_i][1] += e3;
        }
    }

    // reduce neg across the 4 lanes of each quad-row, write partials
    int slot = blockIdx.x * 2 + warp_n;
    #pragma unroll
    for (int m_i = 0; m_i < 2; m_i++) {
        float vlo = neg[m_i][0], vhi = neg[m_i][1];
        vlo += __shfl_xor_sync(0xFFFFFFFFu, vlo, 1);
        vlo += __shfl_xor_sync(0xFFFFFFFFu, vlo, 2);
        vhi += __shfl_xor_sync(0xFFFFFFFFu, vhi, 1);
        vhi += __shfl_xor_sync(0xFFFFFFFFu, vhi, 2);
        if ((lane & 3) == 0) {
            int rlo = row0 + warp_m * 32 + m_i * 16 + qm;
            g_nl_part[(size_t)rlo * (NTILES * 2) + slot] = vlo;
            g_nl_part[(size_t)(rlo + 8) * (NTILES * 2) + slot] = vhi;
        }
    }
}

// ---------------------------------------------------------------------------
// Kernel 3: per-row loss. One warp per row.
__global__ void k_rowloss() {
    int row  = blockIdx.x * 8 + (threadIdx.x >> 5);
    int lane = threadIdx.x & 31;
    const float* p = g_nl_part + (size_t)row * (NTILES * 2);
    float nl = p[lane] + p[lane + 32] + p[lane + 64] + p[lane + 96];
    #pragma unroll
    for (int o = 16; o; o >>= 1) nl += __shfl_xor_sync(0xFFFFFFFFu, nl, o);

    int cnt = g_cnt[row];
    const float* ps = g_pos + (size_t)row * MAX_POS;
    float acc = 0.0f;
    for (int i = lane; i < cnt; i += 32) {
        float t = ps[i];
        acc += log1pf(nl * __expf(-t));
    }
    #pragma unroll
    for (int o = 16; o; o >>= 1) acc += __shfl_xor_sync(0xFFFFFFFFu, acc, o);
    if (lane == 0) g_lm[row] = acc / (float)cnt;
}

// ---------------------------------------------------------------------------
__global__ void k_final(float* __restrict__ out) {
    __shared__ float sm[256];
    float s = 0.0f;
    for (int i = threadIdx.x; i < NN; i += 256) s += g_lm[i];
    sm[threadIdx.x] = s;
    __syncthreads();
    for (int o = 128; o; o >>= 1) {
        if (threadIdx.x < o) sm[threadIdx.x] += sm[threadIdx.x + o];
        __syncthreads();
    }
    if (threadIdx.x == 0) out[0] = sm[0] / (float)NN;
}

// ---------------------------------------------------------------------------
extern "C" void kernel_launch(void* const* d_in, const int* in_sizes, int n_in,
                              void* d_out, int out_size) {
    const float* x = (const float*)d_in[0];
    const float* y = (const float*)d_in[1];

    cudaFuncSetAttribute(k_tile, cudaFuncAttributeMaxDynamicSharedMemorySize, SM_TOT);

    k_ybits<<<(size_t)NN * NN / 32 / 8, 256>>>(y);
    k_normalize<<<NN / 8, 256>>>(x);
    dim3 grid(NTILES, NTILES);
    k_tile<<<grid, 256, SM_TOT>>>();
    k_rowloss<<<NN / 8, 256>>>();
    k_final<<<1, 256>>>((float*)d_out);
}

// round 4
// speedup vs baseline: 2.4262x; 1.7184x over previous
#include <cuda_runtime.h>
#include <cuda_bf16.h>
#include <math.h>
#include <cstdint>

// ContrastiveLoss N=8192 D=128 temp=0.05 — bf16-split HMMA, branchless epilogue
// loss = -mean_i [ (1/ppn_i) * sum_{j: y_ij=1} log( e_ij / (e_ij + nl_i) ) ]
// log(e/(e+nl)) = -log1p(nl*exp(-t)), t = cos/T.
// cos ~= hi.hi^T + hi.lo^T  (bf16 split; dropped lo.hi^T ~9e-5 on cos)

#define NN 8192
#define DD 128
#define INV_T 20.0f
#define MAX_POS 1024
#define NTILES 64            // NN/128 column tiles
#define NWORDS (NN / 32)     // 256 bitmask words per row

__device__ __nv_bfloat16 g_xhi[NN * DD];
__device__ __nv_bfloat16 g_xlo[NN * DD];
__device__ unsigned g_ybits[(size_t)NN * NWORDS];
__device__ int   g_pref[(size_t)NN * NWORDS];          // exclusive prefix of popcounts
__device__ float g_nl_part[(size_t)NN * NTILES * 2];   // 128 partials per row
__device__ int   g_cnt[NN];
__device__ float g_pos[(size_t)NN * MAX_POS];
__device__ float g_lm[NN];

// ---------------------------------------------------------------------------
__device__ __forceinline__ uint32_t smem_u32(const void* p) {
    uint32_t a;
    asm("{ .reg .u64 t; cvta.to.shared.u64 t, %1; cvt.u32.u64 %0, t; }" : "=r"(a) : "l"(p));
    return a;
}
__device__ __forceinline__ void ldmx4(uint32_t* r, uint32_t addr) {
    asm volatile("ldmatrix.sync.aligned.m8n8.x4.shared.b16 {%0,%1,%2,%3}, [%4];"
        : "=r"(r[0]), "=r"(r[1]), "=r"(r[2]), "=r"(r[3]) : "r"(addr));
}
__device__ __forceinline__ void mma_bf16(float* d, const uint32_t* a,
                                         uint32_t b0, uint32_t b1) {
    asm volatile("mma.sync.aligned.m16n8k16.row.col.f32.bf16.bf16.f32 "
        "{%0,%1,%2,%3}, {%4,%5,%6,%7}, {%8,%9}, {%0,%1,%2,%3};"
        : "+f"(d[0]), "+f"(d[1]), "+f"(d[2]), "+f"(d[3])
        : "r"(a[0]), "r"(a[1]), "r"(a[2]), "r"(a[3]), "r"(b0), "r"(b1));
}

// ---------------------------------------------------------------------------
// Kernel 0: binarize y into bitmask.
__global__ void k_ybits(const float* __restrict__ y) {
    size_t idx = (size_t)blockIdx.x * blockDim.x + threadIdx.x;
    unsigned w = __ballot_sync(0xFFFFFFFFu, y[idx] != 0.0f);
    if ((threadIdx.x & 31) == 0) g_ybits[idx >> 5] = w;
}

// ---------------------------------------------------------------------------
// Kernel 1: normalize rows, split into bf16 hi/lo.
__global__ void k_normalize(const float* __restrict__ x) {
    int row  = blockIdx.x * 8 + (threadIdx.x >> 5);
    int lane = threadIdx.x & 31;
    float4 v = ((const float4*)(x + (size_t)row * DD))[lane];
    float ss = v.x * v.x + v.y * v.y + v.z * v.z + v.w * v.w;
    #pragma unroll
    for (int o = 16; o; o >>= 1) ss += __shfl_xor_sync(0xFFFFFFFFu, ss, o);
    float inv = rsqrtf(ss);
    float f[4] = {v.x * inv, v.y * inv, v.z * inv, v.w * inv};
    ushort4 hi4, lo4;
    unsigned short* hp = &hi4.x;
    unsigned short* lp = &lo4.x;
    #pragma unroll
    for (int i = 0; i < 4; i++) {
        __nv_bfloat16 h = __float2bfloat16(f[i]);
        __nv_bfloat16 l = __float2bfloat16(f[i] - __bfloat162float(h));
        hp[i] = *(unsigned short*)&h;
        lp[i] = *(unsigned short*)&l;
    }
    ((ushort4*)(g_xhi + (size_t)row * DD))[lane] = hi4;
    ((ushort4*)(g_xlo + (size_t)row * DD))[lane] = lo4;
}

// ---------------------------------------------------------------------------
// Kernel 2: per-row exclusive prefix of y popcounts. One warp per row.
__global__ void k_ypref() {
    int row  = blockIdx.x * 8 + (threadIdx.x >> 5);
    int lane = threadIdx.x & 31;
    const uint4* wr = (const uint4*)(g_ybits + (size_t)row * NWORDS);
    uint4 a = wr[lane * 2], b = wr[lane * 2 + 1];
    unsigned w8[8] = {a.x, a.y, a.z, a.w, b.x, b.y, b.z, b.w};
    int c[8], tot = 0;
    #pragma unroll
    for (int i = 0; i < 8; i++) { c[i] = __popc(w8[i]); tot += c[i]; }
    // exclusive scan of tot across lanes
    int excl = tot;
    #pragma unroll
    for (int o = 1; o < 32; o <<= 1) {
        int v = __shfl_up_sync(0xFFFFFFFFu, excl, o);
        if (lane >= o) excl += v;
    }
    excl -= tot;
    int run = excl;
    int* pr = g_pref + (size_t)row * NWORDS + lane * 8;
    #pragma unroll
    for (int i = 0; i < 8; i++) { pr[i] = run; run += c[i]; }
    if (lane == 31) g_cnt[row] = run;
}

// ---------------------------------------------------------------------------
// Kernel 3: HMMA tile GEMM + branchless fused epilogue.
// SMEM: A_hi@0 (32K), B_hi@32768 (32K), B_lo@65536 (32K),
//       ybits@98304 (2K), pref@100352 (2K). Rows 256B, chunk c xor (r&7).
#define SM_A   0
#define SM_BH  32768
#define SM_BL  65536
#define SM_YB  98304
#define SM_PF  100352
#define SM_TOT 102400

__global__ void __launch_bounds__(256, 2) k_tile() {
    extern __shared__ char smem[];
    uint32_t sbase = smem_u32(smem);
    const int tid  = threadIdx.x;
    const int wid  = tid >> 5;
    const int lane = tid & 31;
    const int warp_m = wid >> 1;     // 0..3  (32 rows each)
    const int warp_n = wid & 1;      // 0..1  (64 cols each)
    const int row0 = blockIdx.y * 128;
    const int col0 = blockIdx.x * 128;

    // ---- load tiles
    {
        const uint4* ah = (const uint4*)(g_xhi + (size_t)row0 * DD);
        const uint4* bh = (const uint4*)(g_xhi + (size_t)col0 * DD);
        const uint4* bl = (const uint4*)(g_xlo + (size_t)col0 * DD);
        #pragma unroll
        for (int i = 0; i < 8; i++) {
            int idx = tid + i * 256;            // 0..2047
            int r   = idx >> 4;                 // 0..127
            int c   = idx & 15;                 // 16B chunk
            uint32_t so = (uint32_t)r * 256 + (uint32_t)((c ^ (r & 7)) * 16);
            *(uint4*)(smem + SM_A  + so) = ah[idx];
            *(uint4*)(smem + SM_BH + so) = bh[idx];
            *(uint4*)(smem + SM_BL + so) = bl[idx];
        }
        unsigned* yb = (unsigned*)(smem + SM_YB);
        int*      pf = (int*)(smem + SM_PF);
        for (int i = tid; i < 512; i += 256) {
            int r = i >> 2, w = i & 3;
            size_t gi = (size_t)(row0 + r) * NWORDS + blockIdx.x * 4 + w;
            yb[i] = g_ybits[gi];
            pf[i] = g_pref[gi];
        }
    }
    __syncthreads();

    // ---- mainloop
    float acc[2][8][4];
    #pragma unroll
    for (int i = 0; i < 2; i++)
        #pragma unroll
        for (int j = 0; j < 8; j++)
            #pragma unroll
            for (int q = 0; q < 4; q++) acc[i][j][q] = 0.0f;

    const uint32_t lane_row = lane & 15;
    const uint32_t kb  = lane >> 4;
    const uint32_t key = lane & 7;
    const uint32_t a_base = sbase + SM_A  + (warp_m * 32 + lane_row) * 256;
    const uint32_t b_base = sbase + SM_BH + (warp_n * 64 + lane_row) * 256;

    #pragma unroll
    for (int k16 = 0; k16 < 8; k16++) {
        uint32_t ca = (((uint32_t)k16 * 2 + kb) ^ key) * 16;
        uint32_t a0[4], a1[4];
        ldmx4(a0, a_base + ca);
        ldmx4(a1, a_base + 4096 + ca);
        #pragma unroll
        for (int n16 = 0; n16 < 4; n16++) {
            uint32_t bf[4];
            ldmx4(bf, b_base + n16 * 4096 + ca);            // B_hi
            mma_bf16(acc[0][n16 * 2 + 0], a0, bf[0], bf[2]);
            mma_bf16(acc[0][n16 * 2 + 1], a0, bf[1], bf[3]);
            mma_bf16(acc[1][n16 * 2 + 0], a1, bf[0], bf[2]);
            mma_bf16(acc[1][n16 * 2 + 1], a1, bf[1], bf[3]);
            ldmx4(bf, b_base + 32768 + n16 * 4096 + ca);    // B_lo
            mma_bf16(acc[0][n16 * 2 + 0], a0, bf[0], bf[2]);
            mma_bf16(acc[0][n16 * 2 + 1], a0, bf[1], bf[3]);
            mma_bf16(acc[1][n16 * 2 + 0], a1, bf[0], bf[2]);
            mma_bf16(acc[1][n16 * 2 + 1], a1, bf[1], bf[3]);
        }
    }

    // ---- branchless epilogue
    const unsigned* yb = (const unsigned*)(smem + SM_YB);
    const int*      pf = (const int*)(smem + SM_PF);
    const int qm = lane >> 2;            // 0..7
    const int qn = (lane & 3) * 2;       // 0,2,4,6
    float neg[2][2] = {{0.f, 0.f}, {0.f, 0.f}};

    #pragma unroll
    for (int m_i = 0; m_i < 2; m_i++) {
        int rlo = warp_m * 32 + m_i * 16 + qm;
        int rhi = rlo + 8;
        float* gposL = g_pos + (size_t)(row0 + rlo) * MAX_POS;
        float* gposH = g_pos + (size_t)(row0 + rhi) * MAX_POS;
        #pragma unroll
        for (int half = 0; half < 2; half++) {
            int w = warp_n * 2 + half;
            unsigned wordL = yb[rlo * 4 + w];
            unsigned wordH = yb[rhi * 4 + w];
            int      prefL = pf[rlo * 4 + w];
            int      prefH = pf[rhi * 4 + w];
            #pragma unroll
            for (int g = 0; g < 4; g++) {
                int n8 = half * 4 + g;
                const float* d = acc[m_i][n8];
                int p = g * 8 + qn;                // bit position of d[0]/d[2]
                unsigned m0 = 1u << p, m1 = m0 << 1;
                float t0 = d[0] * INV_T, t1 = d[1] * INV_T;
                float t2 = d[2] * INV_T, t3 = d[3] * INV_T;
                float e0 = __expf(t0), e1 = __expf(t1);
                float e2 = __expf(t2), e3 = __expf(t3);
                neg[m_i][0] += (wordL & m0) ? 0.0f : e0;
                neg[m_i][0] += (wordL & m1) ? 0.0f : e1;
                neg[m_i][1] += (wordH & m0) ? 0.0f : e2;
                neg[m_i][1] += (wordH & m1) ? 0.0f : e3;
                if (wordL & m0) gposL[prefL + __popc(wordL & (m0 - 1))] = t0;
                if (wordL & m1) gposL[prefL + __popc(wordL & (m1 - 1))] = t1;
                if (wordH & m0) gposH[prefH + __popc(wordH & (m0 - 1))] = t2;
                if (wordH & m1) gposH[prefH + __popc(wordH & (m1 - 1))] = t3;
            }
        }
    }

    // reduce neg across the 4 lanes of each quad-row, write partials
    int slot = blockIdx.x * 2 + warp_n;
    #pragma unroll
    for (int m_i = 0; m_i < 2; m_i++) {
        float vlo = neg[m_i][0], vhi = neg[m_i][1];
        vlo += __shfl_xor_sync(0xFFFFFFFFu, vlo, 1);
        vlo += __shfl_xor_sync(0xFFFFFFFFu, vlo, 2);
        vhi += __shfl_xor_sync(0xFFFFFFFFu, vhi, 1);
        vhi += __shfl_xor_sync(0xFFFFFFFFu, vhi, 2);
        if ((lane & 3) == 0) {
            int rlo = row0 + warp_m * 32 + m_i * 16 + qm;
            g_nl_part[(size_t)rlo * (NTILES * 2) + slot] = vlo;
            g_nl_part[(size_t)(rlo + 8) * (NTILES * 2) + slot] = vhi;
        }
    }
}

// ---------------------------------------------------------------------------
// Kernel 4: per-row loss. One warp per row.
__global__ void k_rowloss() {
    int row  = blockIdx.x * 8 + (threadIdx.x >> 5);
    int lane = threadIdx.x & 31;
    const float* p = g_nl_part + (size_t)row * (NTILES * 2);
    float nl = p[lane] + p[lane + 32] + p[lane + 64] + p[lane + 96];
    #pragma unroll
    for (int o = 16; o; o >>= 1) nl += __shfl_xor_sync(0xFFFFFFFFu, nl, o);

    int cnt = g_cnt[row];
    const float* ps = g_pos + (size_t)row * MAX_POS;
    float acc = 0.0f;
    for (int i = lane; i < cnt; i += 32) {
        float t = ps[i];
        acc += log1pf(nl * __expf(-t));
    }
    #pragma unroll
    for (int o = 16; o; o >>= 1) acc += __shfl_xor_sync(0xFFFFFFFFu, acc, o);
    if (lane == 0) g_lm[row] = acc / (float)cnt;
}

// ---------------------------------------------------------------------------
__global__ void k_final(float* __restrict__ out) {
    __shared__ float sm[256];
    float s = 0.0f;
    for (int i = threadIdx.x; i < NN; i += 256) s += g_lm[i];
    sm[threadIdx.x] = s;
    __syncthreads();
    for (int o = 128; o; o >>= 1) {
        if (threadIdx.x < o) sm[threadIdx.x] += sm[threadIdx.x + o];
        __syncthreads();
    }
    if (threadIdx.x == 0) out[0] = sm[0] / (float)NN;
}

// ---------------------------------------------------------------------------
extern "C" void kernel_launch(void* const* d_in, const int* in_sizes, int n_in,
                              void* d_out, int out_size) {
    const float* x = (const float*)d_in[0];
    const float* y = (const float*)d_in[1];

    cudaFuncSetAttribute(k_tile, cudaFuncAttributeMaxDynamicSharedMemorySize, SM_TOT);

    k_ybits<<<(size_t)NN * NN / 32 / 8, 256>>>(y);      // idx 0
    k_normalize<<<NN / 8, 256>>>(x);                     // idx 1
    k_ypref<<<NN / 8, 256>>>();                          // idx 2
    dim3 grid(NTILES, NTILES);
    k_tile<<<grid, 256, SM_TOT>>>();                     // idx 3 (ncu slot)
    k_rowloss<<<NN / 8, 256>>>();                        // idx 4
    k_final<<<1, 256>>>((float*)d_out);                  // idx 5
}

// round 6
// speedup vs baseline: 3.9747x; 1.6383x over previous
#include <cuda_runtime.h>
#include <cuda_bf16.h>
#include <math.h>
#include <cstdint>

// ContrastiveLoss N=8192 D=128 temp=0.05 — bf16-split HMMA, symmetric tiles
// loss = -mean_i [ (1/ppn_i) * sum_{j: y_ij=1} log( e_ij / (e_ij + nl_i) ) ]
// log(e/(e+nl)) = -log1p(nl*exp(-t)), t = cos/T.
// cos ~= hi.hi^T + hi.lo^T  (bf16 split; dropped lo.hi^T ~9e-5 on cos)
// S symmetric: only tiles bi<=bj computed; off-diag tiles feed both roles.

#define NN 8192
#define DD 128
#define INV_T 20.0f
#define MAX_POS 1024
#define NWORDS (NN / 32)     // 256 bitmask words per row
#define NSLOT 384            // per-row nl slots: row-role 0..127, col-role 128..383

__device__ __nv_bfloat16 g_xhi[NN * DD];
__device__ __nv_bfloat16 g_xlo[NN * DD];
__device__ unsigned g_ybits[(size_t)NN * NWORDS];
__device__ int   g_pref[(size_t)NN * NWORDS];
__device__ float g_nl_part[(size_t)NN * NSLOT];
__device__ int   g_cnt[NN];
__device__ float g_pos[(size_t)NN * MAX_POS];
__device__ float g_lm[NN];

// ---------------------------------------------------------------------------
__device__ __forceinline__ uint32_t smem_u32(const void* p) {
    uint32_t a;
    asm("{ .reg .u64 t; cvta.to.shared.u64 t, %1; cvt.u32.u64 %0, t; }" : "=r"(a) : "l"(p));
    return a;
}
__device__ __forceinline__ void ldmx4(uint32_t* r, uint32_t addr) {
    asm volatile("ldmatrix.sync.aligned.m8n8.x4.shared.b16 {%0,%1,%2,%3}, [%4];"
        : "=r"(r[0]), "=r"(r[1]), "=r"(r[2]), "=r"(r[3]) : "r"(addr));
}
__device__ __forceinline__ void mma_bf16(float* d, const uint32_t* a,
                                         uint32_t b0, uint32_t b1) {
    asm volatile("mma.sync.aligned.m16n8k16.row.col.f32.bf16.bf16.f32 "
        "{%0,%1,%2,%3}, {%4,%5,%6,%7}, {%8,%9}, {%0,%1,%2,%3};"
        : "+f"(d[0]), "+f"(d[1]), "+f"(d[2]), "+f"(d[3])
        : "r"(a[0]), "r"(a[1]), "r"(a[2]), "r"(a[3]), "r"(b0), "r"(b1));
}

// ---------------------------------------------------------------------------
// Fused y prep: bits + prefix + count, one block per row.
__global__ void k_yprep(const float* __restrict__ y) {
    __shared__ int wtot[8];
    int row = blockIdx.x;
    int t   = threadIdx.x;
    int lane = t & 31, wid = t >> 5;
    const float4* yr = (const float4*)(y + (size_t)row * NN);
    unsigned wbits = 0;
    #pragma unroll
    for (int i = 0; i < 8; i++) {
        float4 v = yr[t * 8 + i];
        unsigned nib = (unsigned)(v.x != 0.0f) | ((unsigned)(v.y != 0.0f) << 1)
                     | ((unsigned)(v.z != 0.0f) << 2) | ((unsigned)(v.w != 0.0f) << 3);
        wbits |= nib << (i * 4);
    }
    g_ybits[(size_t)row * NWORDS + t] = wbits;
    int c = __popc(wbits);
    int inc = c;
    #pragma unroll
    for (int o = 1; o < 32; o <<= 1) {
        int v = __shfl_up_sync(0xFFFFFFFFu, inc, o);
        if (lane >= o) inc += v;
    }
    if (lane == 31) wtot[wid] = inc;
    __syncthreads();
    int wbase = 0;
    #pragma unroll
    for (int w = 0; w < 8; w++) wbase += (w < wid) ? wtot[w] : 0;
    g_pref[(size_t)row * NWORDS + t] = wbase + inc - c;
    if (t == 255) g_cnt[row] = wbase + inc;
}

// ---------------------------------------------------------------------------
__global__ void k_normalize(const float* __restrict__ x) {
    int row  = blockIdx.x * 8 + (threadIdx.x >> 5);
    int lane = threadIdx.x & 31;
    float4 v = ((const float4*)(x + (size_t)row * DD))[lane];
    float ss = v.x * v.x + v.y * v.y + v.z * v.z + v.w * v.w;
    #pragma unroll
    for (int o = 16; o; o >>= 1) ss += __shfl_xor_sync(0xFFFFFFFFu, ss, o);
    float inv = rsqrtf(ss);
    float f[4] = {v.x * inv, v.y * inv, v.z * inv, v.w * inv};
    ushort4 hi4, lo4;
    unsigned short* hp = &hi4.x;
    unsigned short* lp = &lo4.x;
    #pragma unroll
    for (int i = 0; i < 4; i++) {
        __nv_bfloat16 h = __float2bfloat16(f[i]);
        __nv_bfloat16 l = __float2bfloat16(f[i] - __bfloat162float(h));
        hp[i] = *(unsigned short*)&h;
        lp[i] = *(unsigned short*)&l;
    }
    ((ushort4*)(g_xhi + (size_t)row * DD))[lane] = hi4;
    ((ushort4*)(g_xlo + (size_t)row * DD))[lane] = lo4;
}

// ---------------------------------------------------------------------------
__global__ void k_pad() {}   // keeps k_tile at launch index 3 (ncu capture slot)

// ---------------------------------------------------------------------------
// HMMA tile GEMM + dual-role epilogue (tiles bi<=bj only).
#define SM_A   0
#define SM_BH  32768
#define SM_BL  65536
#define SM_YB  98304
#define SM_PF  100352
#define SM_YB2 102400
#define SM_PF2 104448
#define SM_TOT 106496

__global__ void __launch_bounds__(256, 2) k_tile() {
    const int bi = blockIdx.y;
    const int bj = blockIdx.x;
    if (bi > bj) return;
    const bool offdiag = (bi != bj);

    extern __shared__ char smem[];
    uint32_t sbase = smem_u32(smem);
    const int tid  = threadIdx.x;
    const int wid  = tid >> 5;
    const int lane = tid & 31;
    const int warp_m = wid >> 1;
    const int warp_n = wid & 1;
    const int row0 = bi * 128;
    const int col0 = bj * 128;

    // ---- load tiles
    {
        const uint4* ah = (const uint4*)(g_xhi + (size_t)row0 * DD);
        const uint4* bh = (const uint4*)(g_xhi + (size_t)col0 * DD);
        const uint4* bl = (const uint4*)(g_xlo + (size_t)col0 * DD);
        #pragma unroll
        for (int i = 0; i < 8; i++) {
            int idx = tid + i * 256;
            int r   = idx >> 4;
            int c   = idx & 15;
            uint32_t so = (uint32_t)r * 256 + (uint32_t)((c ^ (r & 7)) * 16);
            *(uint4*)(smem + SM_A  + so) = ah[idx];
            *(uint4*)(smem + SM_BH + so) = bh[idx];
            *(uint4*)(smem + SM_BL + so) = bl[idx];
        }
        unsigned* yb = (unsigned*)(smem + SM_YB);
        int*      pf = (int*)(smem + SM_PF);
        for (int i = tid; i < 512; i += 256) {
            int r = i >> 2, w = i & 3;
            size_t gi = (size_t)(row0 + r) * NWORDS + bj * 4 + w;
            yb[i] = g_ybits[gi];
            pf[i] = g_pref[gi];
        }
        if (offdiag) {
            unsigned* yb2 = (unsigned*)(smem + SM_YB2);
            int*      pf2 = (int*)(smem + SM_PF2);
            for (int i = tid; i < 512; i += 256) {
                int r = i >> 2, w = i & 3;
                size_t gi = (size_t)(col0 + r) * NWORDS + bi * 4 + w;
                yb2[i] = g_ybits[gi];
                pf2[i] = g_pref[gi];
            }
        }
    }
    __syncthreads();

    // ---- mainloop
    float acc[2][8][4];
    #pragma unroll
    for (int i = 0; i < 2; i++)
        #pragma unroll
        for (int j = 0; j < 8; j++)
            #pragma unroll
            for (int q = 0; q < 4; q++) acc[i][j][q] = 0.0f;

    const uint32_t lane_row = lane & 15;
    const uint32_t kb  = lane >> 4;
    const uint32_t key = lane & 7;
    const uint32_t a_base = sbase + SM_A  + (warp_m * 32 + lane_row) * 256;
    const uint32_t b_base = sbase + SM_BH + (warp_n * 64 + lane_row) * 256;

    #pragma unroll
    for (int k16 = 0; k16 < 8; k16++) {
        uint32_t ca = (((uint32_t)k16 * 2 + kb) ^ key) * 16;
        uint32_t a0[4], a1[4];
        ldmx4(a0, a_base + ca);
        ldmx4(a1, a_base + 4096 + ca);
        #pragma unroll
        for (int n16 = 0; n16 < 4; n16++) {
            uint32_t bf[4];
            ldmx4(bf, b_base + n16 * 4096 + ca);            // B_hi
            mma_bf16(acc[0][n16 * 2 + 0], a0, bf[0], bf[2]);
            mma_bf16(acc[0][n16 * 2 + 1], a0, bf[1], bf[3]);
            mma_bf16(acc[1][n16 * 2 + 0], a1, bf[0], bf[2]);
            mma_bf16(acc[1][n16 * 2 + 1], a1, bf[1], bf[3]);
            ldmx4(bf, b_base + 32768 + n16 * 4096 + ca);    // B_lo
            mma_bf16(acc[0][n16 * 2 + 0], a0, bf[0], bf[2]);
            mma_bf16(acc[0][n16 * 2 + 1], a0, bf[1], bf[3]);
            mma_bf16(acc[1][n16 * 2 + 0], a1, bf[0], bf[2]);
            mma_bf16(acc[1][n16 * 2 + 1], a1, bf[1], bf[3]);
        }
    }

    // ---- dual-role epilogue
    const unsigned* yb  = (const unsigned*)(smem + SM_YB);
    const int*      pf  = (const int*)(smem + SM_PF);
    const unsigned* yb2 = (const unsigned*)(smem + SM_YB2);
    const int*      pf2 = (const int*)(smem + SM_PF2);
    const int qm = lane >> 2;            // 0..7
    const int qn = (lane & 3) * 2;       // 0,2,4,6
    // row-role accumulators: PER ROW PAIR (rlo -> negLo, rlo+8 -> negHi)
    float negLo[2] = {0.f, 0.f};
    float negHi[2] = {0.f, 0.f};

    #pragma unroll
    for (int n8 = 0; n8 < 8; n8++) {
        const int half = n8 >> 2;
        const int w = warp_n * 2 + half;
        const int p = (n8 & 3) * 8 + qn;
        const unsigned m0 = 1u << p, m1 = m0 << 1;
        const int clA = warp_n * 64 + n8 * 8 + qn;
        unsigned w2c0 = 0, w2c1 = 0;
        int pf2c0 = 0, pf2c1 = 0;
        if (offdiag) {
            w2c0 = yb2[clA * 4 + warp_m];       pf2c0 = pf2[clA * 4 + warp_m];
            w2c1 = yb2[(clA + 1) * 4 + warp_m]; pf2c1 = pf2[(clA + 1) * 4 + warp_m];
        }
        float negc0 = 0.0f, negc1 = 0.0f;
        #pragma unroll
        for (int m_i = 0; m_i < 2; m_i++) {
            const int rlo = warp_m * 32 + m_i * 16 + qm;
            const int rhi = rlo + 8;
            const unsigned wordL = yb[rlo * 4 + w];
            const unsigned wordH = yb[rhi * 4 + w];
            const int prefL = pf[rlo * 4 + w];
            const int prefH = pf[rhi * 4 + w];
            const float* d = acc[m_i][n8];
            float t0 = d[0] * INV_T, t1 = d[1] * INV_T;
            float t2 = d[2] * INV_T, t3 = d[3] * INV_T;
            float e0 = __expf(t0), e1 = __expf(t1);
            float e2 = __expf(t2), e3 = __expf(t3);
            // row role: negLo collects row rlo (e0,e1); negHi row rhi (e2,e3)
            negLo[m_i] += (wordL & m0) ? 0.0f : e0;
            negLo[m_i] += (wordL & m1) ? 0.0f : e1;
            negHi[m_i] += (wordH & m0) ? 0.0f : e2;
            negHi[m_i] += (wordH & m1) ? 0.0f : e3;
            float* gposL = g_pos + (size_t)(row0 + rlo) * MAX_POS;
            float* gposH = g_pos + (size_t)(row0 + rhi) * MAX_POS;
            if (wordL & m0) gposL[prefL + __popc(wordL & (m0 - 1))] = t0;
            if (wordL & m1) gposL[prefL + __popc(wordL & (m1 - 1))] = t1;
            if (wordH & m0) gposH[prefH + __popc(wordH & (m0 - 1))] = t2;
            if (wordH & m1) gposH[prefH + __popc(wordH & (m1 - 1))] = t3;
            // col role (transposed output rows)
            if (offdiag) {
                const unsigned bL = 1u << (rlo & 31);
                const unsigned bH = 1u << (rhi & 31);
                negc0 += (w2c0 & bL) ? 0.0f : e0;
                negc0 += (w2c0 & bH) ? 0.0f : e2;
                negc1 += (w2c1 & bL) ? 0.0f : e1;
                negc1 += (w2c1 & bH) ? 0.0f : e3;
                float* gpc0 = g_pos + (size_t)(col0 + clA) * MAX_POS;
                float* gpc1 = g_pos + (size_t)(col0 + clA + 1) * MAX_POS;
                if (w2c0 & bL) gpc0[pf2c0 + __popc(w2c0 & (bL - 1))] = t0;
                if (w2c0 & bH) gpc0[pf2c0 + __popc(w2c0 & (bH - 1))] = t2;
                if (w2c1 & bL) gpc1[pf2c1 + __popc(w2c1 & (bL - 1))] = t1;
                if (w2c1 & bH) gpc1[pf2c1 + __popc(w2c1 & (bH - 1))] = t3;
            }
        }
        if (offdiag) {
            negc0 += __shfl_xor_sync(0xFFFFFFFFu, negc0, 4);
            negc0 += __shfl_xor_sync(0xFFFFFFFFu, negc0, 8);
            negc0 += __shfl_xor_sync(0xFFFFFFFFu, negc0, 16);
            negc1 += __shfl_xor_sync(0xFFFFFFFFu, negc1, 4);
            negc1 += __shfl_xor_sync(0xFFFFFFFFu, negc1, 8);
            negc1 += __shfl_xor_sync(0xFFFFFFFFu, negc1, 16);
            if (lane < 4) {
                int slot = 128 + bi * 4 + warp_m;
                g_nl_part[(size_t)(col0 + clA) * NSLOT + slot]     = negc0;
                g_nl_part[(size_t)(col0 + clA + 1) * NSLOT + slot] = negc1;
            }
        }
    }

    // row-role neg partials: reduce over lane&3 (same rows, different cols)
    int slotR = bj * 2 + warp_n;
    #pragma unroll
    for (int m_i = 0; m_i < 2; m_i++) {
        float vlo = negLo[m_i], vhi = negHi[m_i];
        vlo += __shfl_xor_sync(0xFFFFFFFFu, vlo, 1);
        vlo += __shfl_xor_sync(0xFFFFFFFFu, vlo, 2);
        vhi += __shfl_xor_sync(0xFFFFFFFFu, vhi, 1);
        vhi += __shfl_xor_sync(0xFFFFFFFFu, vhi, 2);
        if ((lane & 3) == 0) {
            int r = row0 + warp_m * 32 + m_i * 16 + qm;
            g_nl_part[(size_t)r * NSLOT + slotR]       = vlo;
            g_nl_part[(size_t)(r + 8) * NSLOT + slotR] = vhi;
        }
    }
}

// ---------------------------------------------------------------------------
// Per-row loss. Valid slots: [2*br,128) U [128,128+4*br).
__global__ void k_rowloss() {
    int row  = blockIdx.x * 8 + (threadIdx.x >> 5);
    int lane = threadIdx.x & 31;
    int br = row >> 7;
    const float* p = g_nl_part + (size_t)row * NSLOT;
    int lenR = 128 - 2 * br;
    int lenT = lenR + 4 * br;
    float nl = 0.0f;
    for (int i = lane; i < lenT; i += 32) {
        int s = (i < lenR) ? (2 * br + i) : (128 + (i - lenR));
        nl += p[s];
    }
    #pragma unroll
    for (int o = 16; o; o >>= 1) nl += __shfl_xor_sync(0xFFFFFFFFu, nl, o);

    int cnt = g_cnt[row];
    const float* ps = g_pos + (size_t)row * MAX_POS;
    float acc = 0.0f;
    for (int i = lane; i < cnt; i += 32) {
        float t = ps[i];
        acc += log1pf(nl * __expf(-t));
    }
    #pragma unroll
    for (int o = 16; o; o >>= 1) acc += __shfl_xor_sync(0xFFFFFFFFu, acc, o);
    if (lane == 0) g_lm[row] = acc / (float)cnt;
}

// ---------------------------------------------------------------------------
__global__ void k_final(float* __restrict__ out) {
    __shared__ float sm[256];
    float s = 0.0f;
    for (int i = threadIdx.x; i < NN; i += 256) s += g_lm[i];
    sm[threadIdx.x] = s;
    __syncthreads();
    for (int o = 128; o; o >>= 1) {
        if (threadIdx.x < o) sm[threadIdx.x] += sm[threadIdx.x + o];
        __syncthreads();
    }
    if (threadIdx.x == 0) out[0] = sm[0] / (float)NN;
}

// ---------------------------------------------------------------------------
extern "C" void kernel_launch(void* const* d_in, const int* in_sizes, int n_in,
                              void* d_out, int out_size) {
    const float* x = (const float*)d_in[0];
    const float* y = (const float*)d_in[1];

    cudaFuncSetAttribute(k_tile, cudaFuncAttributeMaxDynamicSharedMemorySize, SM_TOT);

    k_yprep<<<NN, 256>>>(y);                             // idx 0
    k_normalize<<<NN / 8, 256>>>(x);                     // idx 1
    k_pad<<<1, 32>>>();                                  // idx 2
    dim3 grid(64, 64);
    k_tile<<<grid, 256, SM_TOT>>>();                     // idx 3 (ncu slot)
    k_rowloss<<<NN / 8, 256>>>();                        // idx 4
    k_final<<<1, 256>>>((float*)d_out);                  // idx 5
}

// round 7
// speedup vs baseline: 4.0611x; 1.0217x over previous
#include <cuda_runtime.h>
#include <cuda_bf16.h>
#include <math.h>
#include <cstdint>

// ContrastiveLoss N=8192 D=128 temp=0.05 — bf16-split HMMA, symmetric tiles,
// smem-reduced dual-role epilogue.
// loss = -mean_i [ (1/ppn_i) * sum_{j: y_ij=1} log( e_ij / (e_ij + nl_i) ) ]
// log(e/(e+nl)) = -log1p(nl*exp(-t)), t = cos/T.
// cos ~= hi.hi^T + hi.lo^T  (bf16 split; dropped lo.hi^T ~9e-5 on cos)

#define NN 8192
#define DD 128
#define INV_T 20.0f
#define MAX_POS 1024
#define NWORDS (NN / 32)
#define NSLOT 192            // row-role slots 0..127, col-role slots 128..191

__device__ __nv_bfloat16 g_xhi[NN * DD];
__device__ __nv_bfloat16 g_xlo[NN * DD];
__device__ unsigned g_ybits[(size_t)NN * NWORDS];
__device__ int   g_pref[(size_t)NN * NWORDS];
__device__ float g_nl_part[(size_t)NN * NSLOT];
__device__ int   g_cnt[NN];
__device__ float g_pos[(size_t)NN * MAX_POS];
__device__ float g_lm[NN];

// ---------------------------------------------------------------------------
__device__ __forceinline__ uint32_t smem_u32(const void* p) {
    uint32_t a;
    asm("{ .reg .u64 t; cvta.to.shared.u64 t, %1; cvt.u32.u64 %0, t; }" : "=r"(a) : "l"(p));
    return a;
}
__device__ __forceinline__ void ldmx4(uint32_t* r, uint32_t addr) {
    asm volatile("ldmatrix.sync.aligned.m8n8.x4.shared.b16 {%0,%1,%2,%3}, [%4];"
        : "=r"(r[0]), "=r"(r[1]), "=r"(r[2]), "=r"(r[3]) : "r"(addr));
}
__device__ __forceinline__ void mma_bf16(float* d, const uint32_t* a,
                                         uint32_t b0, uint32_t b1) {
    asm volatile("mma.sync.aligned.m16n8k16.row.col.f32.bf16.bf16.f32 "
        "{%0,%1,%2,%3}, {%4,%5,%6,%7}, {%8,%9}, {%0,%1,%2,%3};"
        : "+f"(d[0]), "+f"(d[1]), "+f"(d[2]), "+f"(d[3])
        : "r"(a[0]), "r"(a[1]), "r"(a[2]), "r"(a[3]), "r"(b0), "r"(b1));
}

// ---------------------------------------------------------------------------
// Fused y prep: bits + prefix + count, one block per row.
__global__ void k_yprep(const float* __restrict__ y) {
    __shared__ int wtot[8];
    int row = blockIdx.x;
    int t   = threadIdx.x;
    int lane = t & 31, wid = t >> 5;
    const float4* yr = (const float4*)(y + (size_t)row * NN);
    unsigned wbits = 0;
    #pragma unroll
    for (int i = 0; i < 8; i++) {
        float4 v = yr[t * 8 + i];
        unsigned nib = (unsigned)(v.x != 0.0f) | ((unsigned)(v.y != 0.0f) << 1)
                     | ((unsigned)(v.z != 0.0f) << 2) | ((unsigned)(v.w != 0.0f) << 3);
        wbits |= nib << (i * 4);
    }
    g_ybits[(size_t)row * NWORDS + t] = wbits;
    int c = __popc(wbits);
    int inc = c;
    #pragma unroll
    for (int o = 1; o < 32; o <<= 1) {
        int v = __shfl_up_sync(0xFFFFFFFFu, inc, o);
        if (lane >= o) inc += v;
    }
    if (lane == 31) wtot[wid] = inc;
    __syncthreads();
    int wbase = 0;
    #pragma unroll
    for (int w = 0; w < 8; w++) wbase += (w < wid) ? wtot[w] : 0;
    g_pref[(size_t)row * NWORDS + t] = wbase + inc - c;
    if (t == 255) g_cnt[row] = wbase + inc;
}

// ---------------------------------------------------------------------------
__global__ void k_normalize(const float* __restrict__ x) {
    int row  = blockIdx.x * 8 + (threadIdx.x >> 5);
    int lane = threadIdx.x & 31;
    float4 v = ((const float4*)(x + (size_t)row * DD))[lane];
    float ss = v.x * v.x + v.y * v.y + v.z * v.z + v.w * v.w;
    #pragma unroll
    for (int o = 16; o; o >>= 1) ss += __shfl_xor_sync(0xFFFFFFFFu, ss, o);
    float inv = rsqrtf(ss);
    float f[4] = {v.x * inv, v.y * inv, v.z * inv, v.w * inv};
    ushort4 hi4, lo4;
    unsigned short* hp = &hi4.x;
    unsigned short* lp = &lo4.x;
    #pragma unroll
    for (int i = 0; i < 4; i++) {
        __nv_bfloat16 h = __float2bfloat16(f[i]);
        __nv_bfloat16 l = __float2bfloat16(f[i] - __bfloat162float(h));
        hp[i] = *(unsigned short*)&h;
        lp[i] = *(unsigned short*)&l;
    }
    ((ushort4*)(g_xhi + (size_t)row * DD))[lane] = hi4;
    ((ushort4*)(g_xlo + (size_t)row * DD))[lane] = lo4;
}

// ---------------------------------------------------------------------------
__global__ void k_pad() {}   // keeps k_tile at launch index 3 (ncu capture slot)

// ---------------------------------------------------------------------------
// HMMA tile GEMM + dual-role epilogue. 1D triangular grid (2080 blocks).
// Colred scratch reuses the A/B tile smem region after the mainloop:
// float [32][132] at offset 0 (g = warp_m*8+qm rows, 128 cols + pad).
#define SM_A   0
#define SM_BH  32768
#define SM_BL  65536
#define SM_YB  98304
#define SM_PF  100352
#define SM_YB2 102400
#define SM_PF2 104448
#define SM_TOT 106496
#define NBLK   2080          // 64*65/2

__global__ void __launch_bounds__(256, 2) k_tile() {
    // triangular decode: q -> (bi, bj) with bi <= bj
    int bi = 0, rem = blockIdx.x;
    while (rem >= 64 - bi) { rem -= 64 - bi; bi++; }
    const int bj = bi + rem;
    const bool offdiag = (bi != bj);

    extern __shared__ char smem[];
    uint32_t sbase = smem_u32(smem);
    const int tid  = threadIdx.x;
    const int wid  = tid >> 5;
    const int lane = tid & 31;
    const int warp_m = wid >> 1;
    const int warp_n = wid & 1;
    const int row0 = bi * 128;
    const int col0 = bj * 128;

    // ---- load tiles
    {
        const uint4* ah = (const uint4*)(g_xhi + (size_t)row0 * DD);
        const uint4* bh = (const uint4*)(g_xhi + (size_t)col0 * DD);
        const uint4* bl = (const uint4*)(g_xlo + (size_t)col0 * DD);
        #pragma unroll
        for (int i = 0; i < 8; i++) {
            int idx = tid + i * 256;
            int r   = idx >> 4;
            int c   = idx & 15;
            uint32_t so = (uint32_t)r * 256 + (uint32_t)((c ^ (r & 7)) * 16);
            *(uint4*)(smem + SM_A  + so) = ah[idx];
            *(uint4*)(smem + SM_BH + so) = bh[idx];
            *(uint4*)(smem + SM_BL + so) = bl[idx];
        }
        unsigned* yb = (unsigned*)(smem + SM_YB);
        int*      pf = (int*)(smem + SM_PF);
        for (int i = tid; i < 512; i += 256) {
            int r = i >> 2, w = i & 3;
            size_t gi = (size_t)(row0 + r) * NWORDS + bj * 4 + w;
            yb[i] = g_ybits[gi];
            pf[i] = g_pref[gi];
        }
        if (offdiag) {
            unsigned* yb2 = (unsigned*)(smem + SM_YB2);
            int*      pf2 = (int*)(smem + SM_PF2);
            for (int i = tid; i < 512; i += 256) {
                int r = i >> 2, w = i & 3;
                size_t gi = (size_t)(col0 + r) * NWORDS + bi * 4 + w;
                yb2[i] = g_ybits[gi];
                pf2[i] = g_pref[gi];
            }
        }
    }
    __syncthreads();

    // ---- mainloop
    float acc[2][8][4];
    #pragma unroll
    for (int i = 0; i < 2; i++)
        #pragma unroll
        for (int j = 0; j < 8; j++)
            #pragma unroll
            for (int q = 0; q < 4; q++) acc[i][j][q] = 0.0f;

    const uint32_t lane_row = lane & 15;
    const uint32_t kb  = lane >> 4;
    const uint32_t key = lane & 7;
    const uint32_t a_base = sbase + SM_A  + (warp_m * 32 + lane_row) * 256;
    const uint32_t b_base = sbase + SM_BH + (warp_n * 64 + lane_row) * 256;

    #pragma unroll
    for (int k16 = 0; k16 < 8; k16++) {
        uint32_t ca = (((uint32_t)k16 * 2 + kb) ^ key) * 16;
        uint32_t a0[4], a1[4];
        ldmx4(a0, a_base + ca);
        ldmx4(a1, a_base + 4096 + ca);
        #pragma unroll
        for (int n16 = 0; n16 < 4; n16++) {
            uint32_t bf[4];
            ldmx4(bf, b_base + n16 * 4096 + ca);            // B_hi
            mma_bf16(acc[0][n16 * 2 + 0], a0, bf[0], bf[2]);
            mma_bf16(acc[0][n16 * 2 + 1], a0, bf[1], bf[3]);
            mma_bf16(acc[1][n16 * 2 + 0], a1, bf[0], bf[2]);
            mma_bf16(acc[1][n16 * 2 + 1], a1, bf[1], bf[3]);
            ldmx4(bf, b_base + 32768 + n16 * 4096 + ca);    // B_lo
            mma_bf16(acc[0][n16 * 2 + 0], a0, bf[0], bf[2]);
            mma_bf16(acc[0][n16 * 2 + 1], a0, bf[1], bf[3]);
            mma_bf16(acc[1][n16 * 2 + 0], a1, bf[0], bf[2]);
            mma_bf16(acc[1][n16 * 2 + 1], a1, bf[1], bf[3]);
        }
    }
    __syncthreads();   // A/B smem dead after this; colred scratch takes over

    // ---- dual-role epilogue
    const unsigned* yb  = (const unsigned*)(smem + SM_YB);
    const int*      pf  = (const int*)(smem + SM_PF);
    const unsigned* yb2 = (const unsigned*)(smem + SM_YB2);
    const int*      pf2 = (const int*)(smem + SM_PF2);
    float* cr = (float*)(smem + SM_A);   // [32][132]: g = warp_m*8+qm
    const int qm = lane >> 2;            // 0..7
    const int qn = (lane & 3) * 2;       // 0,2,4,6
    const int g  = warp_m * 8 + qm;
    float negLo[2] = {0.f, 0.f};
    float negHi[2] = {0.f, 0.f};

    #pragma unroll
    for (int n8 = 0; n8 < 8; n8++) {
        const int half = n8 >> 2;
        const int w = warp_n * 2 + half;
        const int p = (n8 & 3) * 8 + qn;
        const unsigned m0 = 1u << p, m1 = m0 << 1;
        const int clA = warp_n * 64 + n8 * 8 + qn;
        unsigned w2c0 = 0, w2c1 = 0;
        int pf2c0 = 0, pf2c1 = 0;
        if (offdiag) {
            w2c0 = yb2[clA * 4 + warp_m];       pf2c0 = pf2[clA * 4 + warp_m];
            w2c1 = yb2[(clA + 1) * 4 + warp_m]; pf2c1 = pf2[(clA + 1) * 4 + warp_m];
        }
        float negc0 = 0.0f, negc1 = 0.0f;
        #pragma unroll
        for (int m_i = 0; m_i < 2; m_i++) {
            const int rlo = warp_m * 32 + m_i * 16 + qm;
            const int rhi = rlo + 8;
            const unsigned wordL = yb[rlo * 4 + w];
            const unsigned wordH = yb[rhi * 4 + w];
            const int prefL = pf[rlo * 4 + w];
            const int prefH = pf[rhi * 4 + w];
            const float* d = acc[m_i][n8];
            float t0 = d[0] * INV_T, t1 = d[1] * INV_T;
            float t2 = d[2] * INV_T, t3 = d[3] * INV_T;
            float e0 = __expf(t0), e1 = __expf(t1);
            float e2 = __expf(t2), e3 = __expf(t3);
            negLo[m_i] += (wordL & m0) ? 0.0f : e0;
            negLo[m_i] += (wordL & m1) ? 0.0f : e1;
            negHi[m_i] += (wordH & m0) ? 0.0f : e2;
            negHi[m_i] += (wordH & m1) ? 0.0f : e3;
            float* gposL = g_pos + (size_t)(row0 + rlo) * MAX_POS;
            float* gposH = g_pos + (size_t)(row0 + rhi) * MAX_POS;
            if (wordL & m0) gposL[prefL + __popc(wordL & (m0 - 1))] = t0;
            if (wordL & m1) gposL[prefL + __popc(wordL & (m1 - 1))] = t1;
            if (wordH & m0) gposH[prefH + __popc(wordH & (m0 - 1))] = t2;
            if (wordH & m1) gposH[prefH + __popc(wordH & (m1 - 1))] = t3;
            if (offdiag) {
                const unsigned bL = 1u << (rlo & 31);
                const unsigned bH = 1u << (rhi & 31);
                negc0 += (w2c0 & bL) ? 0.0f : e0;
                negc0 += (w2c0 & bH) ? 0.0f : e2;
                negc1 += (w2c1 & bL) ? 0.0f : e1;
                negc1 += (w2c1 & bH) ? 0.0f : e3;
                float* gpc0 = g_pos + (size_t)(col0 + clA) * MAX_POS;
                float* gpc1 = g_pos + (size_t)(col0 + clA + 1) * MAX_POS;
                if (w2c0 & bL) gpc0[pf2c0 + __popc(w2c0 & (bL - 1))] = t0;
                if (w2c0 & bH) gpc0[pf2c0 + __popc(w2c0 & (bH - 1))] = t2;
                if (w2c1 & bL) gpc1[pf2c1 + __popc(w2c1 & (bL - 1))] = t1;
                if (w2c1 & bH) gpc1[pf2c1 + __popc(w2c1 & (bH - 1))] = t3;
            }
        }
        if (offdiag) {
            cr[g * 132 + clA]     = negc0;   // conflict-free: bank = 4*qm + 2*qnIdx
            cr[g * 132 + clA + 1] = negc1;
        }
    }

    // row-role partials: reduce over lane&3, write both rows of each pair
    int slotR = bj * 2 + warp_n;
    #pragma unroll
    for (int m_i = 0; m_i < 2; m_i++) {
        float vlo = negLo[m_i], vhi = negHi[m_i];
        vlo += __shfl_xor_sync(0xFFFFFFFFu, vlo, 1);
        vlo += __shfl_xor_sync(0xFFFFFFFFu, vlo, 2);
        vhi += __shfl_xor_sync(0xFFFFFFFFu, vhi, 1);
        vhi += __shfl_xor_sync(0xFFFFFFFFu, vhi, 2);
        if ((lane & 3) == 0) {
            int r = row0 + warp_m * 32 + m_i * 16 + qm;
            g_nl_part[(size_t)r * NSLOT + slotR]       = vlo;
            g_nl_part[(size_t)(r + 8) * NSLOT + slotR] = vhi;
        }
    }

    // col-role reduce: 128 threads, one column each, sum 32 scratch values
    __syncthreads();
    if (offdiag && tid < 128) {
        float s = 0.0f;
        #pragma unroll
        for (int gg = 0; gg < 32; gg++) s += cr[gg * 132 + tid];
        g_nl_part[(size_t)(col0 + tid) * NSLOT + 128 + bi] = s;
    }
}

// ---------------------------------------------------------------------------
// Per-row loss. Valid slots for row in block br: [2br,128) U [128,128+br).
__global__ void k_rowloss() {
    int row  = blockIdx.x * 8 + (threadIdx.x >> 5);
    int lane = threadIdx.x & 31;
    int br = row >> 7;
    const float* p = g_nl_part + (size_t)row * NSLOT;
    int lenR = 128 - 2 * br;
    int lenT = lenR + br;
    float nl = 0.0f;
    for (int i = lane; i < lenT; i += 32) {
        int s = (i < lenR) ? (2 * br + i) : (128 + (i - lenR));
        nl += p[s];
    }
    #pragma unroll
    for (int o = 16; o; o >>= 1) nl += __shfl_xor_sync(0xFFFFFFFFu, nl, o);

    int cnt = g_cnt[row];
    const float* ps = g_pos + (size_t)row * MAX_POS;
    float acc = 0.0f;
    for (int i = lane; i < cnt; i += 32) {
        float t = ps[i];
        acc += log1pf(nl * __expf(-t));
    }
    #pragma unroll
    for (int o = 16; o; o >>= 1) acc += __shfl_xor_sync(0xFFFFFFFFu, acc, o);
    if (lane == 0) g_lm[row] = acc / (float)cnt;
}

// ---------------------------------------------------------------------------
__global__ void k_final(float* __restrict__ out) {
    __shared__ float sm[256];
    float s = 0.0f;
    for (int i = threadIdx.x; i < NN; i += 256) s += g_lm[i];
    sm[threadIdx.x] = s;
    __syncthreads();
    for (int o = 128; o; o >>= 1) {
        if (threadIdx.x < o) sm[threadIdx.x] += sm[threadIdx.x + o];
        __syncthreads();
    }
    if (threadIdx.x == 0) out[0] = sm[0] / (float)NN;
}

// ---------------------------------------------------------------------------
extern "C" void kernel_launch(void* const* d_in, const int* in_sizes, int n_in,
                              void* d_out, int out_size) {
    const float* x = (const float*)d_in[0];
    const float* y = (const float*)d_in[1];

    cudaFuncSetAttribute(k_tile, cudaFuncAttributeMaxDynamicSharedMemorySize, SM_TOT);

    k_yprep<<<NN, 256>>>(y);                             // idx 0
    k_normalize<<<NN / 8, 256>>>(x);                     // idx 1
    k_pad<<<1, 32>>>();                                  // idx 2
    k_tile<<<NBLK, 256, SM_TOT>>>();                     // idx 3 (ncu slot)
    k_rowloss<<<NN / 8, 256>>>();                        // idx 4
    k_final<<<1, 256>>>((float*)d_out);                  // idx 5
}

// round 8
// speedup vs baseline: 4.5380x; 1.1174x over previous
#include <cuda_runtime.h>
#include <cuda_bf16.h>
#include <math.h>
#include <cstdint>

// ContrastiveLoss N=8192 D=128 temp=0.05 — plain-bf16 HMMA, symmetric tiles.
// loss = -mean_i [ (1/ppn_i) * sum_{j: y_ij=1} log( e_ij / (e_ij + nl_i) ) ]
// log(e/(e+nl)) = -log1p(nl*exp(-t)), t = cos/T.
// cos in bf16 (rounding error ~1.4e-4 -> loss err ~1e-5, gate is 1e-3).

#define NN 8192
#define DD 128
#define INV_T 20.0f
#define MAX_POS 1024
#define NWORDS (NN / 32)
#define NSLOT 192            // row-role slots 0..127, col-role slots 128..191

__device__ __nv_bfloat16 g_xhi[NN * DD];
__device__ unsigned g_ybits[(size_t)NN * NWORDS];
__device__ int   g_pref[(size_t)NN * NWORDS];
__device__ float g_nl_part[(size_t)NN * NSLOT];
__device__ int   g_cnt[NN];
__device__ float g_pos[(size_t)NN * MAX_POS];
__device__ float g_lm[NN];

// ---------------------------------------------------------------------------
__device__ __forceinline__ uint32_t smem_u32(const void* p) {
    uint32_t a;
    asm("{ .reg .u64 t; cvta.to.shared.u64 t, %1; cvt.u32.u64 %0, t; }" : "=r"(a) : "l"(p));
    return a;
}
__device__ __forceinline__ void ldmx4(uint32_t* r, uint32_t addr) {
    asm volatile("ldmatrix.sync.aligned.m8n8.x4.shared.b16 {%0,%1,%2,%3}, [%4];"
        : "=r"(r[0]), "=r"(r[1]), "=r"(r[2]), "=r"(r[3]) : "r"(addr));
}
__device__ __forceinline__ void mma_bf16(float* d, const uint32_t* a,
                                         uint32_t b0, uint32_t b1) {
    asm volatile("mma.sync.aligned.m16n8k16.row.col.f32.bf16.bf16.f32 "
        "{%0,%1,%2,%3}, {%4,%5,%6,%7}, {%8,%9}, {%0,%1,%2,%3};"
        : "+f"(d[0]), "+f"(d[1]), "+f"(d[2]), "+f"(d[3])
        : "r"(a[0]), "r"(a[1]), "r"(a[2]), "r"(a[3]), "r"(b0), "r"(b1));
}

// ---------------------------------------------------------------------------
// Fused y prep: bits + prefix + count, one block per row.
__global__ void k_yprep(const float* __restrict__ y) {
    __shared__ int wtot[8];
    int row = blockIdx.x;
    int t   = threadIdx.x;
    int lane = t & 31, wid = t >> 5;
    const float4* yr = (const float4*)(y + (size_t)row * NN);
    unsigned wbits = 0;
    #pragma unroll
    for (int i = 0; i < 8; i++) {
        float4 v = yr[t * 8 + i];
        unsigned nib = (unsigned)(v.x != 0.0f) | ((unsigned)(v.y != 0.0f) << 1)
                     | ((unsigned)(v.z != 0.0f) << 2) | ((unsigned)(v.w != 0.0f) << 3);
        wbits |= nib << (i * 4);
    }
    g_ybits[(size_t)row * NWORDS + t] = wbits;
    int c = __popc(wbits);
    int inc = c;
    #pragma unroll
    for (int o = 1; o < 32; o <<= 1) {
        int v = __shfl_up_sync(0xFFFFFFFFu, inc, o);
        if (lane >= o) inc += v;
    }
    if (lane == 31) wtot[wid] = inc;
    __syncthreads();
    int wbase = 0;
    #pragma unroll
    for (int w = 0; w < 8; w++) wbase += (w < wid) ? wtot[w] : 0;
    g_pref[(size_t)row * NWORDS + t] = wbase + inc - c;
    if (t == 255) g_cnt[row] = wbase + inc;
}

// ---------------------------------------------------------------------------
__global__ void k_normalize(const float* __restrict__ x) {
    int row  = blockIdx.x * 8 + (threadIdx.x >> 5);
    int lane = threadIdx.x & 31;
    float4 v = ((const float4*)(x + (size_t)row * DD))[lane];
    float ss = v.x * v.x + v.y * v.y + v.z * v.z + v.w * v.w;
    #pragma unroll
    for (int o = 16; o; o >>= 1) ss += __shfl_xor_sync(0xFFFFFFFFu, ss, o);
    float inv = rsqrtf(ss);
    float f[4] = {v.x * inv, v.y * inv, v.z * inv, v.w * inv};
    ushort4 hi4;
    unsigned short* hp = &hi4.x;
    #pragma unroll
    for (int i = 0; i < 4; i++) {
        __nv_bfloat16 h = __float2bfloat16(f[i]);
        hp[i] = *(unsigned short*)&h;
    }
    ((ushort4*)(g_xhi + (size_t)row * DD))[lane] = hi4;
}

// ---------------------------------------------------------------------------
__global__ void k_pad() {}   // keeps k_tile at launch index 3 (ncu capture slot)

// ---------------------------------------------------------------------------
// HMMA tile GEMM + dual-role epilogue. 1D triangular grid (2080 blocks).
// SMEM: A@0 (32K), B@32768 (32K), yb@65536, pf@67584, yb2@69632, pf2@71680.
// Colred scratch reuses A region ([32][132] floats) after the mainloop.
#define SM_A   0
#define SM_B   32768
#define SM_YB  65536
#define SM_PF  67584
#define SM_YB2 69632
#define SM_PF2 71680
#define SM_TOT 73728
#define NBLK   2080          // 64*65/2

__global__ void __launch_bounds__(256, 2) k_tile() {
    // triangular decode: q -> (bi, bj) with bi <= bj
    int bi = 0, rem = blockIdx.x;
    while (rem >= 64 - bi) { rem -= 64 - bi; bi++; }
    const int bj = bi + rem;
    const bool offdiag = (bi != bj);

    extern __shared__ char smem[];
    uint32_t sbase = smem_u32(smem);
    const int tid  = threadIdx.x;
    const int wid  = tid >> 5;
    const int lane = tid & 31;
    const int warp_m = wid >> 1;
    const int warp_n = wid & 1;
    const int row0 = bi * 128;
    const int col0 = bj * 128;

    // ---- load tiles
    {
        const uint4* ah = (const uint4*)(g_xhi + (size_t)row0 * DD);
        const uint4* bh = (const uint4*)(g_xhi + (size_t)col0 * DD);
        #pragma unroll
        for (int i = 0; i < 8; i++) {
            int idx = tid + i * 256;
            int r   = idx >> 4;
            int c   = idx & 15;
            uint32_t so = (uint32_t)r * 256 + (uint32_t)((c ^ (r & 7)) * 16);
            *(uint4*)(smem + SM_A + so) = ah[idx];
            *(uint4*)(smem + SM_B + so) = bh[idx];
        }
        unsigned* yb = (unsigned*)(smem + SM_YB);
        int*      pf = (int*)(smem + SM_PF);
        for (int i = tid; i < 512; i += 256) {
            int r = i >> 2, w = i & 3;
            size_t gi = (size_t)(row0 + r) * NWORDS + bj * 4 + w;
            yb[i] = g_ybits[gi];
            pf[i] = g_pref[gi];
        }
        if (offdiag) {
            unsigned* yb2 = (unsigned*)(smem + SM_YB2);
            int*      pf2 = (int*)(smem + SM_PF2);
            for (int i = tid; i < 512; i += 256) {
                int r = i >> 2, w = i & 3;
                size_t gi = (size_t)(col0 + r) * NWORDS + bi * 4 + w;
                yb2[i] = g_ybits[gi];
                pf2[i] = g_pref[gi];
            }
        }
    }
    __syncthreads();

    // ---- mainloop (single bf16 matrix)
    float acc[2][8][4];
    #pragma unroll
    for (int i = 0; i < 2; i++)
        #pragma unroll
        for (int j = 0; j < 8; j++)
            #pragma unroll
            for (int q = 0; q < 4; q++) acc[i][j][q] = 0.0f;

    const uint32_t lane_row = lane & 15;
    const uint32_t kb  = lane >> 4;
    const uint32_t key = lane & 7;
    const uint32_t a_base = sbase + SM_A + (warp_m * 32 + lane_row) * 256;
    const uint32_t b_base = sbase + SM_B + (warp_n * 64 + lane_row) * 256;

    #pragma unroll
    for (int k16 = 0; k16 < 8; k16++) {
        uint32_t ca = (((uint32_t)k16 * 2 + kb) ^ key) * 16;
        uint32_t a0[4], a1[4];
        ldmx4(a0, a_base + ca);
        ldmx4(a1, a_base + 4096 + ca);
        #pragma unroll
        for (int n16 = 0; n16 < 4; n16++) {
            uint32_t bf[4];
            ldmx4(bf, b_base + n16 * 4096 + ca);
            mma_bf16(acc[0][n16 * 2 + 0], a0, bf[0], bf[2]);
            mma_bf16(acc[0][n16 * 2 + 1], a0, bf[1], bf[3]);
            mma_bf16(acc[1][n16 * 2 + 0], a1, bf[0], bf[2]);
            mma_bf16(acc[1][n16 * 2 + 1], a1, bf[1], bf[3]);
        }
    }
    __syncthreads();   // A/B smem dead after this; colred scratch takes over

    // ---- dual-role epilogue
    const unsigned* yb  = (const unsigned*)(smem + SM_YB);
    const int*      pf  = (const int*)(smem + SM_PF);
    const unsigned* yb2 = (const unsigned*)(smem + SM_YB2);
    const int*      pf2 = (const int*)(smem + SM_PF2);
    float* cr = (float*)(smem + SM_A);   // [32][132]: g = warp_m*8+qm
    const int qm = lane >> 2;            // 0..7
    const int qn = (lane & 3) * 2;       // 0,2,4,6
    const int g  = warp_m * 8 + qm;
    float negLo[2] = {0.f, 0.f};
    float negHi[2] = {0.f, 0.f};

    #pragma unroll
    for (int n8 = 0; n8 < 8; n8++) {
        const int half = n8 >> 2;
        const int w = warp_n * 2 + half;
        const int p = (n8 & 3) * 8 + qn;
        const unsigned m0 = 1u << p, m1 = m0 << 1;
        const int clA = warp_n * 64 + n8 * 8 + qn;
        unsigned w2c0 = 0, w2c1 = 0;
        int pf2c0 = 0, pf2c1 = 0;
        if (offdiag) {
            w2c0 = yb2[clA * 4 + warp_m];       pf2c0 = pf2[clA * 4 + warp_m];
            w2c1 = yb2[(clA + 1) * 4 + warp_m]; pf2c1 = pf2[(clA + 1) * 4 + warp_m];
        }
        float negc0 = 0.0f, negc1 = 0.0f;
        #pragma unroll
        for (int m_i = 0; m_i < 2; m_i++) {
            const int rlo = warp_m * 32 + m_i * 16 + qm;
            const int rhi = rlo + 8;
            const unsigned wordL = yb[rlo * 4 + w];
            const unsigned wordH = yb[rhi * 4 + w];
            const int prefL = pf[rlo * 4 + w];
            const int prefH = pf[rhi * 4 + w];
            const float* d = acc[m_i][n8];
            float t0 = d[0] * INV_T, t1 = d[1] * INV_T;
            float t2 = d[2] * INV_T, t3 = d[3] * INV_T;
            float e0 = __expf(t0), e1 = __expf(t1);
            float e2 = __expf(t2), e3 = __expf(t3);
            negLo[m_i] += (wordL & m0) ? 0.0f : e0;
            negLo[m_i] += (wordL & m1) ? 0.0f : e1;
            negHi[m_i] += (wordH & m0) ? 0.0f : e2;
            negHi[m_i] += (wordH & m1) ? 0.0f : e3;
            float* gposL = g_pos + (size_t)(row0 + rlo) * MAX_POS;
            float* gposH = g_pos + (size_t)(row0 + rhi) * MAX_POS;
            if (wordL & m0) gposL[prefL + __popc(wordL & (m0 - 1))] = t0;
            if (wordL & m1) gposL[prefL + __popc(wordL & (m1 - 1))] = t1;
            if (wordH & m0) gposH[prefH + __popc(wordH & (m0 - 1))] = t2;
            if (wordH & m1) gposH[prefH + __popc(wordH & (m1 - 1))] = t3;
            if (offdiag) {
                const unsigned bL = 1u << (rlo & 31);
                const unsigned bH = 1u << (rhi & 31);
                negc0 += (w2c0 & bL) ? 0.0f : e0;
                negc0 += (w2c0 & bH) ? 0.0f : e2;
                negc1 += (w2c1 & bL) ? 0.0f : e1;
                negc1 += (w2c1 & bH) ? 0.0f : e3;
                float* gpc0 = g_pos + (size_t)(col0 + clA) * MAX_POS;
                float* gpc1 = g_pos + (size_t)(col0 + clA + 1) * MAX_POS;
                if (w2c0 & bL) gpc0[pf2c0 + __popc(w2c0 & (bL - 1))] = t0;
                if (w2c0 & bH) gpc0[pf2c0 + __popc(w2c0 & (bH - 1))] = t2;
                if (w2c1 & bL) gpc1[pf2c1 + __popc(w2c1 & (bL - 1))] = t1;
                if (w2c1 & bH) gpc1[pf2c1 + __popc(w2c1 & (bH - 1))] = t3;
            }
        }
        if (offdiag) {
            cr[g * 132 + clA]     = negc0;   // conflict-free: bank = 4*qm + 2*qnIdx
            cr[g * 132 + clA + 1] = negc1;
        }
    }

    // row-role partials
    int slotR = bj * 2 + warp_n;
    #pragma unroll
    for (int m_i = 0; m_i < 2; m_i++) {
        float vlo = negLo[m_i], vhi = negHi[m_i];
        vlo += __shfl_xor_sync(0xFFFFFFFFu, vlo, 1);
        vlo += __shfl_xor_sync(0xFFFFFFFFu, vlo, 2);
        vhi += __shfl_xor_sync(0xFFFFFFFFu, vhi, 1);
        vhi += __shfl_xor_sync(0xFFFFFFFFu, vhi, 2);
        if ((lane & 3) == 0) {
            int r = row0 + warp_m * 32 + m_i * 16 + qm;
            g_nl_part[(size_t)r * NSLOT + slotR]       = vlo;
            g_nl_part[(size_t)(r + 8) * NSLOT + slotR] = vhi;
        }
    }

    // col-role reduce: 128 threads, one column each
    __syncthreads();
    if (offdiag && tid < 128) {
        float s = 0.0f;
        #pragma unroll
        for (int gg = 0; gg < 32; gg++) s += cr[gg * 132 + tid];
        g_nl_part[(size_t)(col0 + tid) * NSLOT + 128 + bi] = s;
    }
}

// ---------------------------------------------------------------------------
// Per-row loss. Valid slots for row in block br: [2br,128) U [128,128+br).
__global__ void k_rowloss() {
    int row  = blockIdx.x * 8 + (threadIdx.x >> 5);
    int lane = threadIdx.x & 31;
    int br = row >> 7;
    const float* p = g_nl_part + (size_t)row * NSLOT;
    int lenR = 128 - 2 * br;
    int lenT = lenR + br;
    float nl = 0.0f;
    for (int i = lane; i < lenT; i += 32) {
        int s = (i < lenR) ? (2 * br + i) : (128 + (i - lenR));
        nl += p[s];
    }
    #pragma unroll
    for (int o = 16; o; o >>= 1) nl += __shfl_xor_sync(0xFFFFFFFFu, nl, o);

    int cnt = g_cnt[row];
    const float* ps = g_pos + (size_t)row * MAX_POS;
    float acc = 0.0f;
    for (int i = lane; i < cnt; i += 32) {
        float t = ps[i];
        acc += log1pf(nl * __expf(-t));
    }
    #pragma unroll
    for (int o = 16; o; o >>= 1) acc += __shfl_xor_sync(0xFFFFFFFFu, acc, o);
    if (lane == 0) g_lm[row] = acc / (float)cnt;
}

// ---------------------------------------------------------------------------
__global__ void k_final(float* __restrict__ out) {
    __shared__ float sm[256];
    float s = 0.0f;
    for (int i = threadIdx.x; i < NN; i += 256) s += g_lm[i];
    sm[threadIdx.x] = s;
    __syncthreads();
    for (int o = 128; o; o >>= 1) {
        if (threadIdx.x < o) sm[threadIdx.x] += sm[threadIdx.x + o];
        __syncthreads();
    }
    if (threadIdx.x == 0) out[0] = sm[0] / (float)NN;
}

// ---------------------------------------------------------------------------
extern "C" void kernel_launch(void* const* d_in, const int* in_sizes, int n_in,
                              void* d_out, int out_size) {
    const float* x = (const float*)d_in[0];
    const float* y = (const float*)d_in[1];

    cudaFuncSetAttribute(k_tile, cudaFuncAttributeMaxDynamicSharedMemorySize, SM_TOT);

    k_yprep<<<NN, 256>>>(y);                             // idx 0
    k_normalize<<<NN / 8, 256>>>(x);                     // idx 1
    k_pad<<<1, 32>>>();                                  // idx 2
    k_tile<<<NBLK, 256, SM_TOT>>>();                     // idx 3 (ncu slot)
    k_rowloss<<<NN / 8, 256>>>();                        // idx 4
    k_final<<<1, 256>>>((float*)d_out);                  // idx 5
}